// round 17
// baseline (speedup 1.0000x reference)
#include <cuda_runtime.h>
#include <stdint.h>

#define Bn 2
#define Nn 4096
#define NPART (Bn*Nn)          // 8192
#define Mn 128
#define RAD 0.1f
#define R2  0.01f
#define MAXC 8192              // fast-path cell-count limit (this input: <=1000)
#define NBLK 128
#define NTHR 256
#define NWARPS (NBLK*NTHR/32)  // 1024

// Output layout (flattened, concatenated in reference return order, all f32)
#define OFF_IDXS 0
#define OFF_NBR  (Bn*Nn)                       // 8192
#define OFF_LOCS (OFF_NBR + Bn*Nn*Mn)          // 1056768
#define OFF_DATA (OFF_LOCS + Bn*Nn*3)          // 1081344

// Scratch (static device arrays only — no runtime allocations)
__device__ uint32_t g_keys[NPART];     // final sorted (cell<<12|idx)
__device__ uint32_t g_skeys[NPART];    // scattered (unstable) keys
__device__ float4   g_locs[NPART];     // sorted locs, .w = |p|^2
__device__ int4     g_gridp[Bn];       // {g0,g1,g2, fastflag}
__device__ unsigned g_bmin[Bn][3] = {{0xFFFFFFFFu,0xFFFFFFFFu,0xFFFFFFFFu},
                                     {0xFFFFFFFFu,0xFFFFFFFFu,0xFFFFFFFFu}};
__device__ unsigned g_bmax[Bn][3] = {{0u,0u,0u},{0u,0u,0u}};
__device__ int      g_start[Bn][MAXC];
__device__ int      g_end[Bn][MAXC];
__device__ int      g_cursor[Bn][MAXC];
__device__ unsigned g_barc[8];         // grid-barrier counters (monotonic)

// ---------------------------------------------------------------------------
// order-preserving float <-> uint encoding (exact min/max via integer atomics)
__device__ __forceinline__ unsigned encf(float f) {
    unsigned u = __float_as_uint(f);
    return (u & 0x80000000u) ? ~u : (u | 0x80000000u);
}
__device__ __forceinline__ float decf(unsigned e) {
    unsigned u = (e & 0x80000000u) ? (e ^ 0x80000000u) : ~e;
    return __uint_as_float(u);
}

// Grid-wide barrier. Counter grows monotonically across graph replays; each
// barrier id receives exactly NBLK arrivals per launch, so base = old -
// old%NBLK marks this launch's epoch (unsigned wrap-safe). 128 blocks on 148
// SMs are always co-resident -> no deadlock.
__device__ __forceinline__ void grid_bar(int id) {
    __syncthreads();
    if (threadIdx.x == 0) {
        __threadfence();
        unsigned old = atomicAdd(&g_barc[id], 1u);
        unsigned base = old - (old % (unsigned)NBLK);
        volatile unsigned* p = &g_barc[id];
        while ((*p - base) < (unsigned)NBLK) { }
    }
    __syncthreads();
}

// Exact floor(u/RAD) with rn semantics, division mostly avoided (verified):
// m = rn(u*10) differs from rn(u/0.1f) by < 9e-6 for m <= ~96.5, so when m is
// >= 1e-4 from the nearest integer floor(m) == floor(rn(u/0.1f)) provably;
// otherwise take the exact division path.
__device__ __forceinline__ float cell_floor(float u) {
    float m = __fmul_rn(u, 10.0f);
    float r = rintf(m);
    if (fabsf(__fsub_rn(m, r)) < 1e-4f)
        return floorf(__fdiv_rn(u, RAD));
    return floorf(m);
}

struct GP { float lo[3], gdm1[3]; int strd[3]; int g0, g1, g2, ncells; };

// Reference-identical grid math (rn-exact) from the encoded bounds.
__device__ __forceinline__ void compute_params(int b, GP& P) {
    float gdv[3];
    #pragma unroll
    for (int d = 0; d < 3; d++) {
        float l = decf(g_bmin[b][d]);
        float u = decf(g_bmax[b][d]);
        float r = __fdiv_rn(__fsub_rn(u, l), RAD);
        r = fminf(fmaxf(r, 0.0f), 96.0f);
        float gdf = ceilf(r);
        float c = __fmul_rn(__fadd_rn(l, u), 0.5f);
        P.lo[d] = __fsub_rn(c, __fmul_rn(__fmul_rn(gdf, RAD), 0.5f));
        float gd = fmaxf(gdf, 1.0f);
        gdv[d] = gd;
        P.gdm1[d] = gd - 1.0f;
    }
    P.g0 = (int)gdv[0]; P.g1 = (int)gdv[1]; P.g2 = (int)gdv[2];
    P.strd[0] = P.g1 * P.g2; P.strd[1] = P.g2; P.strd[2] = 1;
    P.ncells = P.g0 * P.g1 * P.g2;
}

// Gather emit for a particle landing at batch-local sorted position p.
// sq computed ONCE (rn-exact), used on both sides of d2 in neighbors.
__device__ __forceinline__ void emit_particle(
    int b, int p, uint32_t key,
    const float* __restrict__ locs, const float* __restrict__ data,
    float* __restrict__ out)
{
    int ord = (int)(key & 4095u);
    int gid = (b << 12) + p;
    g_keys[gid] = key;

    const float* lp = locs + (size_t)((b << 12) + ord) * 3;
    float x = lp[0], y = lp[1], z = lp[2];
    float sq = __fadd_rn(__fadd_rn(__fmul_rn(x, x), __fmul_rn(y, y)),
                         __fmul_rn(z, z));
    g_locs[gid] = make_float4(x, y, z, sq);

    out[OFF_IDXS + gid] = (float)ord;
    float* lout = out + OFF_LOCS + (size_t)gid * 3;
    lout[0] = x; lout[1] = y; lout[2] = z;

    const float4* dp = (const float4*)(data + (size_t)((b << 12) + ord) * 16);
    float4* dq = (float4*)(out + OFF_DATA + (size_t)gid * 16);
    #pragma unroll
    for (int q = 0; q < 4; q++) dq[q] = dp[q];
}

// Per-particle neighbor scan (verified arithmetic/order: first 128 in-radius,
// ascending sorted index == reference's stable 0/1 argsort).
__device__ __forceinline__ void neighbor_one(
    int b, int i, int lane, int g0, int g1, int g2, float* __restrict__ out)
{
    const float4*   shl = g_locs + (b << 12);
    const uint32_t* shk = g_keys + (b << 12);

    uint32_t mykey = __ldg(&shk[i]);
    int cell = (int)(mykey >> 12);
    int cz = cell % g2;
    int t2 = cell / g2;
    int cy = t2 % g1;
    int cx = t2 / g1;

    int res = 0;
    if (lane < 18) {
        int s  = lane >> 1;
        int dx = s / 3 - 1, dy = s % 3 - 1;
        int nx = cx + dx, ny = cy + dy;
        if (nx >= 0 && nx < g0 && ny >= 0 && ny < g1) {
            int base = (nx * g1 + ny) * g2;
            int zlo = max(cz - 1, 0), zhi = min(cz + 1, g2 - 1);
            uint32_t target = ((uint32_t)((lane & 1) ? (base + zhi + 1)
                                                     : (base + zlo))) << 12;
            int lo = 0, hi = Nn;
            while (lo < hi) {
                int mid = (lo + hi) >> 1;
                if (__ldg(&shk[mid]) < target) lo = mid + 1; else hi = mid;
            }
            res = lo;
        }
    }

    float4 me = __ldg(&shl[i]);
    float* nout = out + OFF_NBR + (size_t)((b << 12) + i) * Mn;
    unsigned lt = (1u << lane) - 1u;

    int count = 0;
    #pragma unroll 1
    for (int s = 0; s < 9; s++) {
        int lo = __shfl_sync(0xffffffffu, res, 2*s);
        int hi = __shfl_sync(0xffffffffu, res, 2*s + 1);
        for (int j0 = lo; j0 < hi; j0 += 32) {
            int j = j0 + lane;
            bool m = false;
            if (j < hi) {
                float4 o = __ldg(&shl[j]);
                float dot = __fadd_rn(__fadd_rn(__fmul_rn(me.x, o.x),
                                                __fmul_rn(me.y, o.y)),
                                      __fmul_rn(me.z, o.z));
                float d2 = __fsub_rn(__fadd_rn(me.w, o.w), __fmul_rn(2.0f, dot));
                m = (d2 <= R2);
            }
            unsigned bal = __ballot_sync(0xffffffffu, m);
            if (m) {
                int pos = count + __popc(bal & lt);
                if (pos < Mn) nout[pos] = (float)j;
            }
            count += __popc(bal);
            if (count >= Mn) goto fill;
        }
    }
fill:
    for (int p = min(count, Mn) + lane; p < Mn; p += 32) nout[p] = -1.0f;
}

// ---------------------------------------------------------------------------
// THE kernel: all phases fused, chip-wide, grid barriers between phases.
// ---------------------------------------------------------------------------
__global__ __launch_bounds__(NTHR) void k_all(const float* __restrict__ locs,
                                              const float* __restrict__ data,
                                              float* __restrict__ out)
{
    int tid = threadIdx.x;
    int gid = blockIdx.x * NTHR + tid;
    int lane = tid & 31, warp = tid >> 5;

    __shared__ float smn[3][8], smx[3][8];
    __shared__ int   wtot[8];

    // ===== P0: bounds (blocks 0..23; 6144 float4s = 8192 particles x 3) =====
    if (blockIdx.x < 24) {
        float4 v = __ldg(((const float4*)locs) + gid);
        float mn[3] = {1e30f, 1e30f, 1e30f};
        float mx[3] = {-1e30f, -1e30f, -1e30f};
        int pat = gid % 3;   // dims of (x,y,z,w) = (p, p+1, p+2, p) mod 3
        if (pat == 0) {
            mn[0] = fminf(v.x, v.w); mx[0] = fmaxf(v.x, v.w);
            mn[1] = v.y; mx[1] = v.y; mn[2] = v.z; mx[2] = v.z;
        } else if (pat == 1) {
            mn[1] = fminf(v.x, v.w); mx[1] = fmaxf(v.x, v.w);
            mn[2] = v.y; mx[2] = v.y; mn[0] = v.z; mx[0] = v.z;
        } else {
            mn[2] = fminf(v.x, v.w); mx[2] = fmaxf(v.x, v.w);
            mn[0] = v.y; mx[0] = v.y; mn[1] = v.z; mx[1] = v.z;
        }
        #pragma unroll
        for (int o = 16; o; o >>= 1) {
            #pragma unroll
            for (int d = 0; d < 3; d++) {
                mn[d] = fminf(mn[d], __shfl_xor_sync(0xffffffffu, mn[d], o));
                mx[d] = fmaxf(mx[d], __shfl_xor_sync(0xffffffffu, mx[d], o));
            }
        }
        if (lane == 0) {
            #pragma unroll
            for (int d = 0; d < 3; d++) { smn[d][warp] = mn[d]; smx[d][warp] = mx[d]; }
        }
        __syncthreads();
        if (tid == 0) {
            int b0 = blockIdx.x / 12;
            #pragma unroll
            for (int d = 0; d < 3; d++) {
                float a = smn[d][0], c = smx[d][0];
                for (int w = 1; w < 8; w++) {
                    a = fminf(a, smn[d][w]); c = fmaxf(c, smx[d][w]);
                }
                atomicMin(&g_bmin[b0][d], encf(a));
                atomicMax(&g_bmax[b0][d], encf(c));
            }
        }
    }
    grid_bar(0);

    // ===== P1: params + keys; zero cursors; publish grid dims =====
    uint32_t mykey = 0;
    int      myb = 0;
    bool     fast = true;
    if (gid < NPART) {
        myb = gid >> 12;
        GP P; compute_params(myb, P);
        fast = (P.ncells <= MAXC);
        const float* lp = locs + (size_t)gid * 3;
        float co[3] = {lp[0], lp[1], lp[2]};
        int flat = 0;
        #pragma unroll
        for (int d = 0; d < 3; d++) {
            float c = cell_floor(__fsub_rn(co[d], P.lo[d]));
            c = fminf(fmaxf(c, 0.0f), P.gdm1[d]);
            flat += (int)c * P.strd[d];
        }
        mykey = ((uint32_t)flat << 12) | (uint32_t)(gid & 4095);
        if (!fast) g_skeys[gid] = mykey;   // fallback path needs unsorted keys
    }
    if (gid < Bn * MAXC) ((int*)g_cursor)[gid] = 0;
    if (blockIdx.x == 0 && tid < Bn) {
        GP P; compute_params(tid, P);
        g_gridp[tid] = make_int4(P.g0, P.g1, P.g2, P.ncells <= MAXC ? 1 : 0);
    }
    grid_bar(1);

    // ===== P2: histogram; reset bounds for next replay =====
    if (gid < NPART && fast) atomicAdd(&g_cursor[myb][mykey >> 12], 1);
    if (blockIdx.x == 2) {
        if (tid < 6)  ((unsigned*)g_bmin)[tid] = 0xFFFFFFFFu;
        else if (tid < 12) ((unsigned*)g_bmax)[tid - 6] = 0u;
    }
    grid_bar(2);

    // ===== P3: scan (blocks 0,1) -> start/end, cursor <- start =====
    if (blockIdx.x < Bn) {
        int b = blockIdx.x;
        int4 G = g_gridp[b];
        if (G.w) {
            int ncells = G.x * G.y * G.z;
            int carry = 0;
            for (int base = 0; base < ncells; base += NTHR * 4) {
                int c0 = base + tid * 4;
                int a[4], ssum = 0;
                #pragma unroll
                for (int j = 0; j < 4; j++) {
                    a[j] = (c0 + j < ncells) ? g_cursor[b][c0 + j] : 0;
                    ssum += a[j];
                }
                int inc = ssum;
                #pragma unroll
                for (int o = 1; o < 32; o <<= 1) {
                    int n = __shfl_up_sync(0xffffffffu, inc, o);
                    if (lane >= o) inc += n;
                }
                if (lane == 31) wtot[warp] = inc;
                __syncthreads();
                int woff = 0, tot = 0;
                #pragma unroll
                for (int q = 0; q < 8; q++) {
                    int v = wtot[q];
                    if (q < warp) woff += v;
                    tot += v;
                }
                int run = carry + woff + (inc - ssum);
                #pragma unroll
                for (int j = 0; j < 4; j++) {
                    if (c0 + j < ncells) {
                        g_start[b][c0 + j]  = run;
                        g_cursor[b][c0 + j] = run;
                        run += a[j];
                        g_end[b][c0 + j]    = run;
                    }
                }
                carry += tot;
                __syncthreads();
            }
        }
    }
    grid_bar(3);

    // ===== P4: scatter (unstable within cell) =====
    if (gid < NPART && fast) {
        int pos = atomicAdd(&g_cursor[myb][mykey >> 12], 1);
        g_skeys[(myb << 12) + pos] = mykey;
    }
    grid_bar(4);

    // ===== P5: parallel rank-in-segment + fused gather emit =====
    // keys unique -> start + (#smaller in segment) == exact stable (cell,idx)
    // position == reference stable argsort. __ldcg: L2 reads (freshness).
    if (gid < NPART) {
        int b = gid >> 12;
        uint32_t key = __ldcg(&g_skeys[gid]);
        int sbase, r = 0;
        if (fast) {
            int c = (int)(key >> 12);
            int s = __ldcg(&g_start[b][c]);
            int e = __ldcg(&g_end[b][c]);
            for (int q = s; q < e; q++)
                r += (__ldcg(&g_skeys[(b << 12) + q]) < key);
            sbase = s;
        } else {
            for (int q = 0; q < Nn; q++)
                r += (__ldcg(&g_skeys[(b << 12) + q]) < key);
            sbase = 0;
        }
        emit_particle(b, sbase + r, key, locs, data, out);
    }
    grid_bar(5);

    // ===== P6: neighbors (1024 warps x 8 particles) =====
    int4 G0 = g_gridp[0];
    int4 G1 = g_gridp[1];
    int gwarp = (blockIdx.x * NTHR + tid) >> 5;
    #pragma unroll 1
    for (int pi = gwarp; pi < NPART; pi += NWARPS) {
        int b = pi >> 12;
        int4 G = b ? G1 : G0;
        neighbor_one(b, pi & 4095, lane, G.x, G.y, G.z, out);
    }
}

// ---------------------------------------------------------------------------
extern "C" void kernel_launch(void* const* d_in, const int* in_sizes, int n_in,
                              void* d_out, int out_size) {
    const float* locs = (const float*)d_in[0];
    const float* data = (const float*)d_in[1];
    float* out = (float*)d_out;
    k_all<<<NBLK, NTHR>>>(locs, data, out);
}